// round 12
// baseline (speedup 1.0000x reference)
#include <cuda_runtime.h>
#include <cuda_bf16.h>
#include <math.h>
#include <stdint.h>

#define HD 128
#define MTILE 128
#define THREADS 512
#define WSTRIDE 136
#define ROWB 272
#define SLOT_BYTES 69632
#define LO_BYTES 34816

#define SM_B0 0
#define SM_B1 SLOT_BYTES
#define SM_A (2 * SLOT_BYTES)
#define SM_SP (3 * SLOT_BYTES)
#define SM_MB (SM_SP + 2048)
#define SM_TOTAL (SM_MB + 16)

// Weight images: slots 0..5 forward (B[n][k]=W[n][k]), 6..11 backward (B[n][k]=W[k][n])
// per slot: [hi 128x136 bf16 | lo 128x136 bf16]
__device__ __align__(16) unsigned char g_wimg[12 * SLOT_BYTES];
__device__ float g_fb[4 * HD];   // bias + sin(t*fw+fb) per forward layer
__device__ float2 g_gb[4 * HD];  // (gamma, beta)
// softplus checkpoints
__device__ float g_s[(size_t)4 * 1024 * 16 * 1024];

__global__ void prep_kernel(const float* __restrict__ t, const float* __restrict__ fw,
                            const float* __restrict__ fb, const float* __restrict__ W_in,
                            const float* __restrict__ Wl, const float* __restrict__ W_out,
                            const float* __restrict__ b_in, const float* __restrict__ bl,
                            const float* __restrict__ gamma, const float* __restrict__ beta) {
    int b = blockIdx.x;
    if (b < 12) {
        int m = b % 6;
        bool fwd = b < 6;
        const float* src = (m == 0) ? W_in : (m <= 4 ? Wl + (m - 1) * HD * HD : W_out);
        __nv_bfloat16* img = reinterpret_cast<__nv_bfloat16*>(g_wimg + (size_t)b * SLOT_BYTES);
        for (int idx = threadIdx.x; idx < HD * HD; idx += blockDim.x) {
            int n = idx >> 7, k = idx & 127;
            float v = fwd ? src[n * HD + k] : src[k * HD + n];
            __nv_bfloat16 h = __float2bfloat16(v);
            float r = v - __bfloat162float(h);
            img[n * WSTRIDE + k] = h;
            img[17408 + n * WSTRIDE + k] = __float2bfloat16(r);
        }
    } else {
        float tv = t[0];
        for (int c = threadIdx.x; c < 4 * HD; c += blockDim.x) {
            int i = c >> 7, cc = c & 127;
            float cv = sinf(tv * fw[c] + fb[c]);
            float bias = (i == 0) ? b_in[cc] : bl[(i - 1) * HD + cc];
            g_fb[c] = bias + cv;
            g_gb[c] = make_float2(gamma[c], beta[c]);
        }
    }
}

__device__ __forceinline__ uint32_t s2u(const void* p) {
    uint32_t a;
    asm("{ .reg .u64 t; cvta.to.shared.u64 t, %1; cvt.u32.u64 %0, t; }" : "=r"(a) : "l"(p));
    return a;
}
__device__ __forceinline__ unsigned packbf(float lo, float hi) {
    unsigned r;
    asm("cvt.rn.bf16x2.f32 %0, %1, %2;" : "=r"(r) : "f"(hi), "f"(lo));
    return r;
}
__device__ __forceinline__ void mma16816(float c[4], unsigned a0, unsigned a1, unsigned a2,
                                         unsigned a3, unsigned b0, unsigned b1) {
    asm volatile(
        "mma.sync.aligned.m16n8k16.row.col.f32.bf16.bf16.f32 "
        "{%0,%1,%2,%3},{%4,%5,%6,%7},{%8,%9},{%0,%1,%2,%3};"
        : "+f"(c[0]), "+f"(c[1]), "+f"(c[2]), "+f"(c[3])
        : "r"(a0), "r"(a1), "r"(a2), "r"(a3), "r"(b0), "r"(b1));
}
#define MBAR_INIT(a, c) \
    asm volatile("mbarrier.init.shared.b64 [%0], %1;" ::"r"(a), "r"(c) : "memory")
#define MBAR_WAIT(a, ph)                                                                      \
    do {                                                                                      \
        uint32_t _done;                                                                       \
        asm volatile(                                                                         \
            "{ .reg .pred p; mbarrier.try_wait.parity.acquire.cta.shared::cta.b64 p, [%1], %2; " \
            "selp.b32 %0, 1, 0, p; }"                                                        \
            : "=r"(_done) : "r"(a), "r"(ph) : "memory");                                      \
        while (!_done) {                                                                      \
            asm volatile(                                                                     \
                "{ .reg .pred p; mbarrier.try_wait.parity.acquire.cta.shared::cta.b64 p, [%1], %2, 0x989680; " \
                "selp.b32 %0, 1, 0, p; }"                                                    \
                : "=r"(_done) : "r"(a), "r"(ph) : "memory");                                  \
        }                                                                                     \
    } while (0)

__device__ __forceinline__ void bulkStage(uint32_t dstS, int slot, uint32_t mbar) {
    asm volatile("mbarrier.arrive.expect_tx.shared.b64 _, [%0], %1;" ::"r"(mbar),
                 "r"((unsigned)SLOT_BYTES)
                 : "memory");
    asm volatile(
        "cp.async.bulk.shared::cluster.global.mbarrier::complete_tx::bytes [%0], [%1], %2, [%3];" ::
            "r"(dstS),
        "l"((const char*)g_wimg + (size_t)slot * SLOT_BYTES), "r"((unsigned)SLOT_BYTES),
        "r"(mbar)
        : "memory");
}

__device__ __forceinline__ float softplus_f(float x) {
    return fmaxf(x, 0.f) + __logf(1.f + __expf(-fabsf(x)));
}
__device__ __forceinline__ float qred(float v) {
    v += __shfl_xor_sync(0xffffffffu, v, 1);
    v += __shfl_xor_sync(0xffffffffu, v, 2);
    return v;
}

// GEMM: each warp computes 16 rows x 64 cols (its half), A and B from smem via ldmatrix.
__device__ __forceinline__ void gemmStep(uint32_t bB, uint32_t aB, float C[8][4]) {
#pragma unroll
    for (int n = 0; n < 8; n++)
#pragma unroll
        for (int q = 0; q < 4; q++) C[n][q] = 0.f;
#pragma unroll
    for (int kt = 0; kt < 8; kt++) {
        unsigned ah0, ah1, ah2, ah3, al0, al1, al2, al3;
        asm volatile("ldmatrix.sync.aligned.m8n8.x4.shared.b16 {%0,%1,%2,%3}, [%4];"
                     : "=r"(ah0), "=r"(ah1), "=r"(ah2), "=r"(ah3)
                     : "r"(aB + kt * 32));
        asm volatile("ldmatrix.sync.aligned.m8n8.x4.shared.b16 {%0,%1,%2,%3}, [%4];"
                     : "=r"(al0), "=r"(al1), "=r"(al2), "=r"(al3)
                     : "r"(aB + LO_BYTES + kt * 32));
#pragma unroll
        for (int nt = 0; nt < 8; nt++) {
            unsigned b0, b1, b2, b3;
            asm volatile("ldmatrix.sync.aligned.m8n8.x4.shared.b16 {%0,%1,%2,%3}, [%4];"
                         : "=r"(b0), "=r"(b1), "=r"(b2), "=r"(b3)
                         : "r"(bB + nt * 2176 + kt * 32));
            mma16816(C[nt], ah0, ah1, ah2, ah3, b0, b1);
            mma16816(C[nt], ah0, ah1, ah2, ah3, b2, b3);
            mma16816(C[nt], al0, al1, al2, al3, b0, b1);
        }
    }
}

// write one (x,y) col-pair as bf16 hi/lo into the A tile
__device__ __forceinline__ void writeActRow(uint32_t addr, float x, float y) {
    unsigned h = packbf(x, y);
    float r0 = x - __uint_as_float(h << 16);
    float r1 = y - __uint_as_float(h & 0xFFFF0000u);
    unsigned l = packbf(r0, r1);
    asm volatile("st.shared.b32 [%0], %1;" ::"r"(addr), "r"(h) : "memory");
    asm volatile("st.shared.b32 [%0], %1;" ::"r"(addr + LO_BYTES), "r"(l) : "memory");
}
__device__ __forceinline__ void writeAct(uint32_t a0, const float v[8][4]) {
#pragma unroll
    for (int nt = 0; nt < 8; nt++) {
        writeActRow(a0 + nt * 16, v[nt][0], v[nt][1]);
        writeActRow(a0 + 2176 + nt * 16, v[nt][2], v[nt][3]);
    }
}

__global__ __launch_bounds__(THREADS, 1) void fused_kernel(
    const float* __restrict__ p, const float* __restrict__ w, const float* __restrict__ bl,
    const float* __restrict__ b_out, float* __restrict__ dp, float* __restrict__ dw, int nblk) {
    extern __shared__ __align__(16) char sm[];
    const int tid = threadIdx.x, warp = tid >> 5, lane = tid & 31;
    const int wp = warp >> 1, wh = warp & 1, lg = lane >> 2, li = lane & 3;
    const int rowA = wp * 16 + lg;                    // local rows: rowA, rowA+8
    const size_t grow = (size_t)blockIdx.x * MTILE + rowA;
    const int cB = wh * 64 + 2 * li;                  // first col of this thread's pairs
    const uint32_t smb = s2u(sm);
    const uint32_t mb0 = smb + SM_MB, mb1 = mb0 + 8;
    float2* sP = reinterpret_cast<float2*>(sm + SM_SP);

    const uint32_t bFragOff =
        (uint32_t)((lane & 7) * ROWB + ((lane >> 3) & 1) * 16 + (lane >> 4) * LO_BYTES +
                   wh * 8 * 2176);
    const uint32_t aFrag =
        smb + SM_A + (uint32_t)((wp * 16 + (lane & 15)) * ROWB + ((lane >> 4) & 1) * 16);
    const uint32_t actA = smb + SM_A + (uint32_t)(rowA * ROWB + cB * 2);

    if (tid == 0) {
        MBAR_INIT(mb0, 1);
        MBAR_INIT(mb1, 1);
        asm volatile("fence.proxy.async.shared::cta;" ::: "memory");
    }
    __syncthreads();
    if (tid == 0) {
        bulkStage(smb + SM_B0, 0, mb0);
        bulkStage(smb + SM_B1, 1, mb1);
    }

    float v[8][4];
    // prologue: p -> A tile
#pragma unroll
    for (int nt = 0; nt < 8; nt++) {
        float2 x0 = *reinterpret_cast<const float2*>(&p[grow * HD + cB + nt * 8]);
        float2 x1 = *reinterpret_cast<const float2*>(&p[(grow + 8) * HD + cB + nt * 8]);
        v[nt][0] = x0.x; v[nt][1] = x0.y; v[nt][2] = x1.x; v[nt][3] = x1.y;
    }
    writeAct(actA, v);
    __syncthreads();

    float C[8][4];
    float mus[4][2], invs[4][2];
    int ph0 = 0, ph1 = 0;

#pragma unroll 1
    for (int g = 0; g < 12; g++) {
        uint32_t bbase = smb + ((g & 1) ? SM_B1 : SM_B0) + bFragOff;
        if (g & 1) { MBAR_WAIT(mb1, ph1); ph1 ^= 1; }
        else       { MBAR_WAIT(mb0, ph0); ph0 ^= 1; }
        gemmStep(bbase, aFrag, C);
        __syncthreads();
        if (tid == 0 && g + 2 < 12) {
            int gg = g + 2;
            bulkStage(smb + ((g & 1) ? SM_B1 : SM_B0), (gg < 6) ? gg : 17 - gg,
                      (g & 1) ? mb1 : mb0);
        }

        if (g < 4) {  // forward LN layer g
            float p10 = 0.f, p20 = 0.f, p11 = 0.f, p21 = 0.f;
#pragma unroll
            for (int nt = 0; nt < 8; nt++) {
                float2 fb2 = *reinterpret_cast<const float2*>(&g_fb[g * HD + cB + nt * 8]);
                float s0 = softplus_f(C[nt][0] + fb2.x);
                float s1 = softplus_f(C[nt][1] + fb2.y);
                float s2 = softplus_f(C[nt][2] + fb2.x);
                float s3 = softplus_f(C[nt][3] + fb2.y);
                v[nt][0] = s0; v[nt][1] = s1; v[nt][2] = s2; v[nt][3] = s3;
                p10 += s0 + s1; p20 += s0 * s0 + s1 * s1;
                p11 += s2 + s3; p21 += s2 * s2 + s3 * s3;
            }
            {
                float4* dst = reinterpret_cast<float4*>(g_s) +
                              ((size_t)(g * nblk + blockIdx.x) * 8) * THREADS + tid;
#pragma unroll
                for (int nt = 0; nt < 8; nt++)
                    dst[nt * THREADS] = make_float4(v[nt][0], v[nt][1], v[nt][2], v[nt][3]);
            }
            p10 = qred(p10); p20 = qred(p20); p11 = qred(p11); p21 = qred(p21);
            if (li == 0) {
                sP[warp * 16 + lg] = make_float2(p10, p20);
                sP[warp * 16 + lg + 8] = make_float2(p11, p21);
            }
            __syncthreads();
            float2 o0 = sP[(warp ^ 1) * 16 + lg];
            float2 o1 = sP[(warp ^ 1) * 16 + lg + 8];
            float mu0 = (p10 + o0.x) * (1.f / HD);
            float mu1 = (p11 + o1.x) * (1.f / HD);
            float inv0 = rsqrtf((p20 + o0.y) * (1.f / HD) - mu0 * mu0 + 1e-5f);
            float inv1 = rsqrtf((p21 + o1.y) * (1.f / HD) - mu1 * mu1 + 1e-5f);
            mus[g][0] = mu0; mus[g][1] = mu1; invs[g][0] = inv0; invs[g][1] = inv1;
#pragma unroll
            for (int nt = 0; nt < 8; nt++) {
                float4 gb = *reinterpret_cast<const float4*>(&g_gb[g * HD + cB + nt * 8]);
                v[nt][0] = (v[nt][0] - mu0) * inv0 * gb.x + gb.y;
                v[nt][1] = (v[nt][1] - mu0) * inv0 * gb.z + gb.w;
                v[nt][2] = (v[nt][2] - mu1) * inv1 * gb.x + gb.y;
                v[nt][3] = (v[nt][3] - mu1) * inv1 * gb.z + gb.w;
            }
            writeAct(actA, v);
        } else if (g == 4) {
#pragma unroll
            for (int nt = 0; nt < 8; nt++) {
                float2 b2 = *reinterpret_cast<const float2*>(&bl[3 * HD + cB + nt * 8]);
                v[nt][0] = C[nt][0] + b2.x; v[nt][1] = C[nt][1] + b2.y;
                v[nt][2] = C[nt][2] + b2.x; v[nt][3] = C[nt][3] + b2.y;
            }
            writeAct(actA, v);
        } else if (g == 5) {
#pragma unroll
            for (int nt = 0; nt < 8; nt++) {
                float2 b2 = *reinterpret_cast<const float2*>(&b_out[cB + nt * 8]);
                *reinterpret_cast<float2*>(&dp[grow * HD + cB + nt * 8]) =
                    make_float2(C[nt][0] + b2.x, C[nt][1] + b2.y);
                *reinterpret_cast<float2*>(&dp[(grow + 8) * HD + cB + nt * 8]) =
                    make_float2(C[nt][2] + b2.x, C[nt][3] + b2.y);
            }
#pragma unroll
            for (int nt = 0; nt < 8; nt++) {
                float2 x0 = *reinterpret_cast<const float2*>(&w[grow * HD + cB + nt * 8]);
                float2 x1 = *reinterpret_cast<const float2*>(&w[(grow + 8) * HD + cB + nt * 8]);
                v[nt][0] = x0.x; v[nt][1] = x0.y; v[nt][2] = x1.x; v[nt][3] = x1.y;
            }
            writeAct(actA, v);
        } else if (g == 6) {
#pragma unroll
            for (int nt = 0; nt < 8; nt++)
#pragma unroll
                for (int q = 0; q < 4; q++) v[nt][q] = C[nt][q];
            writeAct(actA, v);
        } else if (g < 11) {  // backward LN layer i
            int i = 10 - g;
            float4 sarr[8];
            {
                const float4* src = reinterpret_cast<const float4*>(g_s) +
                                    ((size_t)(i * nblk + blockIdx.x) * 8) * THREADS + tid;
#pragma unroll
                for (int nt = 0; nt < 8; nt++) sarr[nt] = src[nt * THREADS];
            }
            float mu0 = mus[i][0], mu1 = mus[i][1], inv0 = invs[i][0], inv1 = invs[i][1];
            float p10 = 0.f, p20 = 0.f, p11 = 0.f, p21 = 0.f;
#pragma unroll
            for (int nt = 0; nt < 8; nt++) {
                float4 gb = *reinterpret_cast<const float4*>(&g_gb[i * HD + cB + nt * 8]);
                float gx0 = C[nt][0] * gb.x, gx1 = C[nt][1] * gb.z;
                float gx2 = C[nt][2] * gb.x, gx3 = C[nt][3] * gb.z;
                C[nt][0] = gx0; C[nt][1] = gx1; C[nt][2] = gx2; C[nt][3] = gx3;
                p10 += gx0 + gx1;
                p20 += gx0 * (sarr[nt].x - mu0) + gx1 * (sarr[nt].y - mu0);
                p11 += gx2 + gx3;
                p21 += gx2 * (sarr[nt].z - mu1) + gx3 * (sarr[nt].w - mu1);
            }
            p10 = qred(p10); p20 = qred(p20); p11 = qred(p11); p21 = qred(p21);
            if (li == 0) {
                sP[warp * 16 + lg] = make_float2(p10, p20);
                sP[warp * 16 + lg + 8] = make_float2(p11, p21);
            }
            __syncthreads();
            float2 o0 = sP[(warp ^ 1) * 16 + lg];
            float2 o1 = sP[(warp ^ 1) * 16 + lg + 8];
            float m10 = (p10 + o0.x) * (1.f / HD), m20 = (p20 + o0.y) * inv0 * (1.f / HD);
            float m11 = (p11 + o1.x) * (1.f / HD), m21 = (p21 + o1.y) * inv1 * (1.f / HD);
#pragma unroll
            for (int nt = 0; nt < 8; nt++) {
                float s0 = sarr[nt].x, s1 = sarr[nt].y, s2 = sarr[nt].z, s3 = sarr[nt].w;
                v[nt][0] = inv0 * (C[nt][0] - m10 - (s0 - mu0) * inv0 * m20) * (1.f - __expf(-s0));
                v[nt][1] = inv0 * (C[nt][1] - m10 - (s1 - mu0) * inv0 * m20) * (1.f - __expf(-s1));
                v[nt][2] = inv1 * (C[nt][2] - m11 - (s2 - mu1) * inv1 * m21) * (1.f - __expf(-s2));
                v[nt][3] = inv1 * (C[nt][3] - m11 - (s3 - mu1) * inv1 * m21) * (1.f - __expf(-s3));
            }
            writeAct(actA, v);
        } else {  // g == 11: dw = -C
#pragma unroll
            for (int nt = 0; nt < 8; nt++) {
                *reinterpret_cast<float2*>(&dw[grow * HD + cB + nt * 8]) =
                    make_float2(-C[nt][0], -C[nt][1]);
                *reinterpret_cast<float2*>(&dw[(grow + 8) * HD + cB + nt * 8]) =
                    make_float2(-C[nt][2], -C[nt][3]);
            }
        }
        if (g < 11) __syncthreads();
    }
}

extern "C" void kernel_launch(void* const* d_in, const int* in_sizes, int n_in,
                              void* d_out, int out_size) {
    const float* t     = (const float*)d_in[0];
    const float* p     = (const float*)d_in[1];
    const float* w     = (const float*)d_in[2];
    const float* W_in  = (const float*)d_in[3];
    const float* b_in  = (const float*)d_in[4];
    const float* fw    = (const float*)d_in[5];
    const float* fb    = (const float*)d_in[6];
    const float* gamma = (const float*)d_in[7];
    const float* beta  = (const float*)d_in[8];
    const float* Wl    = (const float*)d_in[9];
    const float* bl    = (const float*)d_in[10];
    const float* W_out = (const float*)d_in[11];
    const float* b_out = (const float*)d_in[12];

    int nrows = in_sizes[1] / HD;
    int nblk = nrows / MTILE;
    float* dp = (float*)d_out;
    float* dw = dp + (size_t)nrows * HD;

    cudaFuncSetAttribute(fused_kernel, cudaFuncAttributeMaxDynamicSharedMemorySize, SM_TOTAL);

    prep_kernel<<<13, 256>>>(t, fw, fb, W_in, Wl, W_out, b_in, bl, gamma, beta);
    fused_kernel<<<nblk, THREADS, SM_TOTAL>>>(p, w, bl, b_out, dp, dw, nblk);
}